// round 14
// baseline (speedup 1.0000x reference)
#include <cuda_runtime.h>
#include <cuda_fp16.h>
#include <math.h>
#include <stdint.h>

#define BCN   512          // B*C
#define LBK   1024
#define PREDN 256
#define TOT   1280
#define DEL   64
#define DPD   128
#define NKR   971          // key rows (T)
#define NQR   244          // query rows (UP)
#define NROWS 1215         // NKR + NQR
#define FLATN 15616        // NQR*DEL
#define NSPL  8            // mlp1 split-K

// ---------------- scratch ------------------------------------------------------
__device__ __half g_kh[(size_t)BCN * NROWS * DPD];   // LN output, hi plane
__device__ __half g_kl[(size_t)BCN * NROWS * DPD];   // LN output, lo plane
__device__ __half g_fh[(size_t)BCN * FLATN];         // attention out, hi plane
__device__ __half g_fl[(size_t)BCN * FLATN];         // attention out, lo plane
__device__ __half g_w1h[(size_t)PREDN * FLATN];      // W1^T hi plane [n][k]
__device__ __half g_w1l[(size_t)PREDN * FLATN];      // W1^T lo plane [n][k]
__device__ __half g_wph[DPD * DEL];                  // Wp^T hi plane [e][d]
__device__ __half g_wpl[DPD * DEL];                  // Wp^T lo plane [e][d]
__device__ float  g_hpart[NSPL * BCN * PREDN];       // split-K partials

__device__ __forceinline__ float series_at(const float* __restrict__ lb,
                                           const float* __restrict__ fp,
                                           int bc, int i) {
    return (i < LBK) ? lb[bc * LBK + i] : fp[bc * PREDN + (i - LBK)];
}

// ---------------- PTX helpers ---------------------------------------------------
__device__ __forceinline__ uint32_t smem_u32(const void* p) {
    uint32_t a;
    asm("{ .reg .u64 t; cvta.to.shared.u64 t, %1; cvt.u32.u64 %0, t; }" : "=r"(a) : "l"(p));
    return a;
}

#define LDSM4(R, A) \
    asm volatile("ldmatrix.sync.aligned.m8n8.x4.shared.b16 {%0,%1,%2,%3}, [%4];" \
        : "=r"((R)[0]), "=r"((R)[1]), "=r"((R)[2]), "=r"((R)[3]) : "r"(A))

#define CP_A16(dst, src, sz) \
    asm volatile("cp.async.cg.shared.global [%0], [%1], 16, %2;" \
        :: "r"(dst), "l"(src), "r"(sz))
#define CP_COMMIT() asm volatile("cp.async.commit_group;" ::: "memory")
#define CP_WAIT0()  asm volatile("cp.async.wait_group 0;" ::: "memory")

__device__ __forceinline__ void mma16(float c[4], const uint32_t a[4], const uint32_t b[2]) {
    asm volatile(
        "mma.sync.aligned.m16n8k16.row.col.f32.f16.f16.f32 "
        "{%0,%1,%2,%3}, {%4,%5,%6,%7}, {%8,%9}, {%0,%1,%2,%3};\n"
        : "+f"(c[0]), "+f"(c[1]), "+f"(c[2]), "+f"(c[3])
        : "r"(a[0]), "r"(a[1]), "r"(a[2]), "r"(a[3]), "r"(b[0]), "r"(b[1]));
}

__device__ __forceinline__ void mma16h(uint32_t c[2], const uint32_t a[4], const uint32_t b[2]) {
    asm volatile(
        "mma.sync.aligned.m16n8k16.row.col.f16.f16.f16.f16 "
        "{%0,%1}, {%2,%3,%4,%5}, {%6,%7}, {%0,%1};\n"
        : "+r"(c[0]), "+r"(c[1])
        : "r"(a[0]), "r"(a[1]), "r"(a[2]), "r"(a[3]), "r"(b[0]), "r"(b[1]));
}

__device__ __forceinline__ void merge_cor(float c[4], const uint32_t cor[2]) {
    float2 a = __half22float2(*(const __half2*)&cor[0]);
    float2 b = __half22float2(*(const __half2*)&cor[1]);
    c[0] += a.x; c[1] += a.y; c[2] += b.x; c[3] += b.y;
}

__device__ __forceinline__ void hsplit2(float x0, float x1, uint32_t& hi, uint32_t& lo) {
    __half h0 = __float2half_rn(x0), h1 = __float2half_rn(x1);
    __half l0 = __float2half_rn(x0 - __half2float(h0));
    __half l1 = __float2half_rn(x1 - __half2float(h1));
    __half2 H = __halves2half2(h0, h1), L = __halves2half2(l0, l1);
    hi = *(uint32_t*)&H; lo = *(uint32_t*)&L;
}

__device__ __forceinline__ void hsplit1(float x, __half& h, __half& l) {
    h = __float2half_rn(x);
    l = __float2half_rn(x - __half2float(h));
}

__device__ __forceinline__ float ex2(float x) {
    float r;
    asm("ex2.approx.f32 %0, %1;" : "=f"(r) : "f"(x));
    return r;
}

// ---------------- Kernel W0: split Wp into transposed fp16 planes -------------
__global__ void __launch_bounds__(256)
conv_wp_kernel(const float* __restrict__ Wp) {
    int i = blockIdx.x * 256 + threadIdx.x;   // 8192 total
    int d = i >> 7, e = i & 127;
    float w = Wp[i];
    __half h, l; hsplit1(w, h, l);
    g_wph[e * DEL + d] = h;
    g_wpl[e * DEL + d] = l;
}

// ---------------- Kernel A: proj + PE + LN (256 rows/block) -------------------
#define PKW 36
#define PROJ_HDR_W (TOT + 256 + 256 + 128 + 128 + 128)
#define PROJ_BYTES (PROJ_HDR_W * 4 + 4 * 128 * PKW * 4)

__global__ void __launch_bounds__(256)
proj_ln_kernel(const float* __restrict__ lb, const float* __restrict__ fp,
               const float* __restrict__ bp, const float* __restrict__ pe,
               const float* __restrict__ lng, const float* __restrict__ lnb) {
    extern __shared__ float psm[];
    float* ssp   = psm;
    float* red_s = ssp + TOT;
    float* red_q = red_s + 256;
    float* gl_s  = red_q + 256;
    float* lb_s  = gl_s + 128;
    float* bp_s  = lb_s + 128;
    uint32_t* Ah = (uint32_t*)(bp_s + 128);
    uint32_t* Al = Ah + 128 * PKW;
    uint32_t* Bh = Al + 128 * PKW;
    uint32_t* Bl = Bh + 128 * PKW;

    const int bc  = blockIdx.y;
    const int tid = threadIdx.x;
    const int warp = tid >> 5, lane = tid & 31;
    const int g = lane >> 2, t = lane & 3;
    const int wm = warp >> 1, wn = warp & 1;
    const int R0 = wm * 32, C0 = wn * 64;

    for (int i = tid; i < TOT; i += 256) ssp[i] = series_at(lb, fp, bc, i);
    if (tid < 128) { gl_s[tid] = lng[tid]; lb_s[tid] = lnb[tid]; bp_s[tid] = bp[tid]; }

    __half* Ahb = (__half*)Ah;
    __half* Alb = (__half*)Al;
    __half* Bhb = (__half*)Bh;
    __half* Blb = (__half*)Bl;

    {
        const uint4* wph = (const uint4*)g_wph;
        const uint4* wpl = (const uint4*)g_wpl;
        for (int i = tid; i < 2048; i += 256) {
            int pl = i >> 10, r = (i >> 3) & 127, c = i & 7;
            uint4 v = pl ? wpl[r * 8 + c] : wph[r * 8 + c];
            uint4* dst = (uint4*)((pl ? Blb : Bhb) + r * (2 * PKW));
            dst[c] = v;
        }
    }
    __syncthreads();

    for (int h2 = 0; h2 < 2; ++h2) {
        const int t0 = blockIdx.x * 256 + h2 * 128;
        if (t0 >= NROWS) break;

        for (int i = tid; i < 128 * DEL; i += 256) {
            int r = i >> 6, d = i & 63;
            int tt = t0 + r;
            float x = 0.f;
            if (tt < NROWS) {
                int s0 = (tt < NKR) ? tt : (tt + 1);
                x = ssp[s0 + d];
            }
            __half h, l; hsplit1(x, h, l);
            Ahb[r * (2 * PKW) + d] = h;
            Alb[r * (2 * PKW) + d] = l;
        }
        __syncthreads();

        float cC[2][8][4];
        uint32_t cr[2][8][2];
        #pragma unroll
        for (int mi = 0; mi < 2; ++mi)
            #pragma unroll
            for (int ni = 0; ni < 8; ++ni) {
                #pragma unroll
                for (int i = 0; i < 4; ++i) cC[mi][ni][i] = 0.f;
                cr[mi][ni][0] = 0u; cr[mi][ni][1] = 0u;
            }

        #pragma unroll
        for (int e8 = 0; e8 < 4; ++e8) {
            uint32_t ah[2][4], al_[2][4];
            #pragma unroll
            for (int mi = 0; mi < 2; ++mi) {
                int r0 = (R0 + mi * 16 + g) * PKW + e8 * 8 + t;
                ah[mi][0] = Ah[r0];           ah[mi][1] = Ah[r0 + 8 * PKW];
                ah[mi][2] = Ah[r0 + 4];       ah[mi][3] = Ah[r0 + 8 * PKW + 4];
                al_[mi][0] = Al[r0];          al_[mi][1] = Al[r0 + 8 * PKW];
                al_[mi][2] = Al[r0 + 4];      al_[mi][3] = Al[r0 + 8 * PKW + 4];
            }
            uint32_t bh[8][2], bl2[8][2];
            #pragma unroll
            for (int ni = 0; ni < 8; ++ni) {
                int n0 = (C0 + ni * 8 + g) * PKW + e8 * 8 + t;
                bh[ni][0] = Bh[n0];  bh[ni][1] = Bh[n0 + 4];
                bl2[ni][0] = Bl[n0]; bl2[ni][1] = Bl[n0 + 4];
            }
            #pragma unroll
            for (int mi = 0; mi < 2; ++mi)
                #pragma unroll
                for (int ni = 0; ni < 8; ++ni) {
                    mma16(cC[mi][ni], ah[mi], bh[ni]);
                    mma16h(cr[mi][ni], ah[mi], bl2[ni]);
                    mma16h(cr[mi][ni], al_[mi], bh[ni]);
                }
        }
        #pragma unroll
        for (int mi = 0; mi < 2; ++mi)
            #pragma unroll
            for (int ni = 0; ni < 8; ++ni) merge_cor(cC[mi][ni], cr[mi][ni]);

        float ps_[2][2], pq_[2][2];
        #pragma unroll
        for (int mi = 0; mi < 2; ++mi)
            #pragma unroll
            for (int h = 0; h < 2; ++h) { ps_[mi][h] = 0.f; pq_[mi][h] = 0.f; }

        #pragma unroll
        for (int mi = 0; mi < 2; ++mi)
            #pragma unroll
            for (int h = 0; h < 2; ++h) {
                int row = R0 + mi * 16 + g + 8 * h;
                int grow = t0 + row;
                const float* perow = pe + (size_t)grow * DPD;
                #pragma unroll
                for (int ni = 0; ni < 8; ++ni) {
                    int col = C0 + ni * 8 + 2 * t;
                    float2 p2 = *(const float2*)(perow + col);
                    float x0 = cC[mi][ni][2 * h]     + bp_s[col]     + p2.x;
                    float x1 = cC[mi][ni][2 * h + 1] + bp_s[col + 1] + p2.y;
                    cC[mi][ni][2 * h] = x0; cC[mi][ni][2 * h + 1] = x1;
                    ps_[mi][h] += x0 + x1;
                    pq_[mi][h] += x0 * x0 + x1 * x1;
                }
            }
        #pragma unroll
        for (int mi = 0; mi < 2; ++mi)
            #pragma unroll
            for (int h = 0; h < 2; ++h) {
                ps_[mi][h] += __shfl_xor_sync(0xffffffffu, ps_[mi][h], 1);
                ps_[mi][h] += __shfl_xor_sync(0xffffffffu, ps_[mi][h], 2);
                pq_[mi][h] += __shfl_xor_sync(0xffffffffu, pq_[mi][h], 1);
                pq_[mi][h] += __shfl_xor_sync(0xffffffffu, pq_[mi][h], 2);
            }
        if (t == 0) {
            #pragma unroll
            for (int mi = 0; mi < 2; ++mi)
                #pragma unroll
                for (int h = 0; h < 2; ++h) {
                    int row = R0 + mi * 16 + g + 8 * h;
                    red_s[wn * 128 + row] = ps_[mi][h];
                    red_q[wn * 128 + row] = pq_[mi][h];
                }
        }
        __syncthreads();

        #pragma unroll
        for (int mi = 0; mi < 2; ++mi)
            #pragma unroll
            for (int h = 0; h < 2; ++h) {
                int row = R0 + mi * 16 + g + 8 * h;
                int grow = t0 + row;
                if (grow >= NROWS) continue;
                float sm_ = red_s[row] + red_s[128 + row];
                float sq_ = red_q[row] + red_q[128 + row];
                float mean = sm_ * (1.f / DPD);
                float var  = sq_ * (1.f / DPD) - mean * mean;
                float inv  = rsqrtf(var + 1e-5f);
                size_t base = ((size_t)bc * NROWS + grow) * DPD;
                #pragma unroll
                for (int ni = 0; ni < 8; ++ni) {
                    int col = C0 + ni * 8 + 2 * t;
                    float y0 = (cC[mi][ni][2 * h]     - mean) * inv * gl_s[col]     + lb_s[col];
                    float y1 = (cC[mi][ni][2 * h + 1] - mean) * inv * gl_s[col + 1] + lb_s[col + 1];
                    uint32_t hw, lw; hsplit2(y0, y1, hw, lw);
                    *(uint32_t*)(g_kh + base + col) = hw;
                    *(uint32_t*)(g_kl + base + col) = lw;
                }
            }
        __syncthreads();   // red_s/A reuse ordering for next half
    }
}

// ---------------- Kernel B: attention (chained V loads, mask-specialized) -----
#define KW 68
#define VPN 642
#define QH_W (TOT + 4 * VPN)              // 3848 words
#define KB_W (QH_W + 2 * 128 * KW)        // 21256 words
#define ATT_W (KB_W + 4 * 128 * KW)       // 56072 words
#define ASM_BYTES (ATT_W * 4)             // 224288 bytes

__global__ void __launch_bounds__(256, 1)
attn_kernel(const float* __restrict__ lb, const float* __restrict__ fp) {
    extern __shared__ float sm[];
    float* ss     = sm;                        // [1280]
    uint32_t* vph = (uint32_t*)(sm + TOT);     // [2*VPN]
    uint32_t* vpl = vph + 2 * VPN;             // [2*VPN]
    uint32_t* qh  = (uint32_t*)sm + QH_W;      // [128*KW]
    uint32_t* ql  = qh + 128 * KW;

    const uint32_t sbase = smem_u32(sm);
    const uint32_t kb_a  = sbase + KB_W * 4;

    const int bc  = blockIdx.y;
    const int qt0 = blockIdx.x * 128;
    const int tid = threadIdx.x;
    const int warp = tid >> 5, lane = tid & 31;
    const int g = lane >> 2, t = lane & 3;
    const int q0 = warp * 16;

    const int lA = lane & 15, wA = (lane >> 4) * 4;
    const int lB = (lane & 7) + ((lane >> 4) & 1) * 8;
    const int wB = ((lane >> 3) & 1) * 4;

    auto issue_chunk = [&](int ch) {
        if (ch >= 8) return;
        const int buf = ch & 1;
        const uint32_t dkh = kb_a + buf * 69632u;
        const uint32_t dkl = dkh + 34816u;
        const int kt0 = ch * 128;
        const uint4* gh = (const uint4*)(g_kh + ((size_t)bc * NROWS + kt0) * DPD);
        const uint4* gl = (const uint4*)(g_kl + ((size_t)bc * NROWS + kt0) * DPD);
        #pragma unroll
        for (int it = 0; it < 8; ++it) {
            int i = tid + it * 256;
            int r = i >> 4, c = i & 15;
            int sz = (kt0 + r < NKR) ? 16 : 0;
            uint32_t d = (uint32_t)((r * 17 + c) * 16);
            CP_A16(dkh + d, gh + r * 16 + c, sz);
            CP_A16(dkl + d, gl + r * 16 + c, sz);
        }
        CP_COMMIT();
    };

    issue_chunk(0);

    for (int i = tid; i < TOT; i += 256) ss[i] = series_at(lb, fp, bc, i);

    {
        const uint4* qhs = (const uint4*)(g_kh + ((size_t)bc * NROWS + NKR + qt0) * DPD);
        const uint4* qls = (const uint4*)(g_kl + ((size_t)bc * NROWS + NKR + qt0) * DPD);
        uint4 z = make_uint4(0u, 0u, 0u, 0u);
        for (int i = tid; i < 128 * 16; i += 256) {
            int r = i >> 4, c = i & 15;
            bool v = (qt0 + r) < NQR;
            ((uint4*)qh)[r * 17 + c] = v ? qhs[r * 16 + c] : z;
            ((uint4*)ql)[r * 17 + c] = v ? qls[r * 16 + c] : z;
        }
    }

    for (int i = tid; i < 2 * 641; i += 256) {
        int par = (i >= 641);
        int w = i - par * 641;
        int e0 = 2 * w + par;
        float x0 = (e0 < TOT) ? ss[e0] : 0.f;
        float x1 = (e0 + 1 < TOT) ? ss[e0 + 1] : 0.f;
        uint32_t hw, lw; hsplit2(x0, x1, hw, lw);
        vph[par * VPN + w] = hw;
        vpl[par * VPN + w] = lw;
    }

    const uint32_t aQH = smem_u32(qh) + (((q0 + lA) * KW + wA) << 2);
    const uint32_t aQL = smem_u32(ql) + (((q0 + lA) * KW + wA) << 2);
    uint32_t rbK[8];
    #pragma unroll
    for (int n2 = 0; n2 < 8; ++n2)
        rbK[n2] = (((n2 * 16 + lB) * KW + wB) << 2);

    // parity of V element index is lane-constant: idx0 = kt0+1 + (even) + g
    const int vpar = (1 + g) & 1;
    const uint32_t vparoff = (uint32_t)(vpar * VPN);

    float cO[8][4];
    uint32_t crO[8][2];
    float rs0 = 0.f, rs1 = 0.f;
    #pragma unroll
    for (int ni = 0; ni < 8; ++ni) {
        #pragma unroll
        for (int i = 0; i < 4; ++i) cO[ni][i] = 0.f;
        crO[ni][0] = 0u; crO[ni][1] = 0u;
    }

    const float C2  = 0.1275174324f;     // log2(e)/sqrt(128)
    const float OFF = -8.6561702453f;    // -6*log2(e)

    for (int ch = 0; ch < 8; ++ch) {
        const int kt0 = ch * 128;
        const int buf = ch & 1;
        const uint32_t kh_a = kb_a + buf * 69632u;
        const uint32_t kl_a = kh_a + 34816u;
        const bool needmask = (kt0 + 128 > NKR);

        CP_WAIT0();
        __syncthreads();   // K chunk ready; Q/V visible (ch0); buf^1 free
        issue_chunk(ch + 1);

        const int vb0 = kt0 + 1;
        #pragma unroll
        for (int j = 0; j < 8; ++j) {
            float cS[2][4];
            uint32_t crS[2][2];
            #pragma unroll
            for (int jj = 0; jj < 2; ++jj) {
                #pragma unroll
                for (int i = 0; i < 4; ++i) cS[jj][i] = 0.f;
                crS[jj][0] = 0u; crS[jj][1] = 0u;
            }

            #pragma unroll
            for (int e8 = 0; e8 < 8; ++e8) {
                uint32_t a_h[4], a_l[4], b_h[4], b_l[4];
                LDSM4(a_h, aQH + e8 * 32);
                LDSM4(a_l, aQL + e8 * 32);
                LDSM4(b_h, kh_a + rbK[j] + e8 * 32);
                LDSM4(b_l, kl_a + rbK[j] + e8 * 32);
                mma16(cS[0], a_h, b_h);
                mma16h(crS[0], a_h, b_l);
                mma16h(crS[0], a_l, b_h);
                mma16(cS[1], a_h, b_h + 2);
                mma16h(crS[1], a_h, b_l + 2);
                mma16h(crS[1], a_l, b_h + 2);
            }

            float p[8];
            if (!needmask) {
                #pragma unroll
                for (int jj = 0; jj < 2; ++jj) {
                    merge_cor(cS[jj], crS[jj]);
                    float p0 = ex2(fmaf(cS[jj][0], C2, OFF));
                    float p1 = ex2(fmaf(cS[jj][1], C2, OFF));
                    float p2 = ex2(fmaf(cS[jj][2], C2, OFF));
                    float p3 = ex2(fmaf(cS[jj][3], C2, OFF));
                    rs0 += p0 + p1;
                    rs1 += p2 + p3;
                    p[4 * jj + 0] = p0; p[4 * jj + 1] = p1;
                    p[4 * jj + 2] = p2; p[4 * jj + 3] = p3;
                }
            } else {
                #pragma unroll
                for (int jj = 0; jj < 2; ++jj) {
                    merge_cor(cS[jj], crS[jj]);
                    int c0 = kt0 + 16 * j + 8 * jj + 2 * t;
                    float p0 = (c0     < NKR) ? ex2(fmaf(cS[jj][0], C2, OFF)) : 0.f;
                    float p1 = (c0 + 1 < NKR) ? ex2(fmaf(cS[jj][1], C2, OFF)) : 0.f;
                    float p2 = (c0     < NKR) ? ex2(fmaf(cS[jj][2], C2, OFF)) : 0.f;
                    float p3 = (c0 + 1 < NKR) ? ex2(fmaf(cS[jj][3], C2, OFF)) : 0.f;
                    rs0 += p0 + p1;
                    rs1 += p2 + p3;
                    p[4 * jj + 0] = p0; p[4 * jj + 1] = p1;
                    p[4 * jj + 2] = p2; p[4 * jj + 3] = p3;
                }
            }
            uint32_t ah[4], al[4];
            hsplit2(p[0], p[1], ah[0], al[0]);
            hsplit2(p[2], p[3], ah[1], al[1]);
            hsplit2(p[4], p[5], ah[2], al[2]);
            hsplit2(p[6], p[7], ah[3], al[3]);

            // ---- PV with chained V loads: vh[ni][1] == vh[ni+1][0] ----
            const uint32_t wb = (uint32_t)((vb0 + j * 16 + 2 * t + g) >> 1) + vparoff;
            uint32_t vh0 = vph[wb], vl0 = vpl[wb];
            #pragma unroll
            for (int ni = 0; ni < 8; ++ni) {
                uint32_t vh1 = vph[wb + 4 * (ni + 1)];
                uint32_t vl1 = vpl[wb + 4 * (ni + 1)];
                uint32_t vhp[2] = {vh0, vh1};
                uint32_t vlp[2] = {vl0, vl1};
                mma16(cO[ni], ah, vhp);
                mma16h(crO[ni], ah, vlp);
                mma16h(crO[ni], al, vhp);
                vh0 = vh1; vl0 = vl1;
            }
        }
    }

    rs0 += __shfl_xor_sync(0xffffffffu, rs0, 1);
    rs0 += __shfl_xor_sync(0xffffffffu, rs0, 2);
    rs1 += __shfl_xor_sync(0xffffffffu, rs1, 1);
    rs1 += __shfl_xor_sync(0xffffffffu, rs1, 2);
    const float inv0 = 1.f / rs0;
    const float inv1 = 1.f / rs1;
    const int r0 = qt0 + q0 + g;

    #pragma unroll
    for (int ni = 0; ni < 8; ++ni) {
        merge_cor(cO[ni], crO[ni]);
        int d = ni * 8 + 2 * t;
        uint32_t hw, lw;
        if (r0 < NQR) {
            hsplit2(cO[ni][0] * inv0, cO[ni][1] * inv0, hw, lw);
            *(uint32_t*)(g_fh + (size_t)bc * FLATN + (size_t)r0 * DEL + d) = hw;
            *(uint32_t*)(g_fl + (size_t)bc * FLATN + (size_t)r0 * DEL + d) = lw;
        }
        if (r0 + 8 < NQR) {
            hsplit2(cO[ni][2] * inv1, cO[ni][3] * inv1, hw, lw);
            *(uint32_t*)(g_fh + (size_t)bc * FLATN + (size_t)(r0 + 8) * DEL + d) = hw;
            *(uint32_t*)(g_fl + (size_t)bc * FLATN + (size_t)(r0 + 8) * DEL + d) = lw;
        }
    }
}

// ---------------- Kernel W1: split W1, coalesced via smem tile transpose ------
__global__ void __launch_bounds__(256)
conv_w1_kernel(const float* __restrict__ W1) {
    __shared__ float tile[64][65];
    const int k0 = blockIdx.x * 64;
    const int n0 = blockIdx.y * 64;
    const int tid = threadIdx.x;

    #pragma unroll
    for (int i = 0; i < 16; ++i) {
        int idx = tid + i * 256;
        int r = idx >> 6, c = idx & 63;
        tile[r][c] = W1[(size_t)(k0 + r) * PREDN + n0 + c];
    }
    __syncthreads();

    #pragma unroll
    for (int i = 0; i < 16; ++i) {
        int idx = tid + i * 256;
        int n = idx >> 6, k = idx & 63;
        float v = tile[k][n];
        __half h, l; hsplit1(v, h, l);
        size_t off = (size_t)(n0 + n) * FLATN + k0 + k;
        g_w1h[off] = h;
        g_w1l[off] = l;
    }
}

// ---------------- Kernel C1: flat @ W1 (ldmatrix + cp.async db) ---------------
#define MROW 20
__global__ void __launch_bounds__(256)
mlp1_kernel() {
    __shared__ __align__(16) uint32_t MS[2][4][64 * MROW];

    const int n0  = blockIdx.x * 64;
    const int bc0 = blockIdx.y * 64;
    const int z   = blockIdx.z;
    const int tid = threadIdx.x;
    const int warp = tid >> 5, lane = tid & 31;
    const int g = lane >> 2, t = lane & 3;
    const int lA = lane & 15, wA = (lane >> 4) * 4;
    const int lB = (lane & 7) + ((lane >> 4) & 1) * 8, wB = ((lane >> 3) & 1) * 4;
    const int m0  = (warp >> 1) * 16;
    const int n0w = (warp & 1) * 32;
    const int r4 = tid >> 2, c4 = tid & 3;

    auto issue = [&](int ch) {
        if (ch >= 61) return;
        const int buf = ch & 1;
        const int k0 = z * 1952 + ch * 32;
        const uint4* sh[4] = {
            (const uint4*)(g_fh  + (size_t)(bc0 + r4) * FLATN + k0),
            (const uint4*)(g_fl  + (size_t)(bc0 + r4) * FLATN + k0),
            (const uint4*)(g_w1h + (size_t)(n0 + r4) * FLATN + k0),
            (const uint4*)(g_w1l + (size_t)(n0 + r4) * FLATN + k0)};
        uint32_t d = (uint32_t)((r4 * 5 + c4) * 16);
        #pragma unroll
        for (int p = 0; p < 4; ++p)
            CP_A16(smem_u32(MS[buf][p]) + d, sh[p] + c4, 16);
        CP_COMMIT();
    };

    float cM[4][4];
    uint32_t crM[4][2];
    #pragma unroll
    for (int ni = 0; ni < 4; ++ni) {
        #pragma unroll
        for (int i = 0; i < 4; ++i) cM[ni][i] = 0.f;
        crM[ni][0] = 0u; crM[ni][1] = 0u;
    }

    const uint32_t rbA = (((m0 + lA) * MROW + wA) << 2);
    const uint32_t rbB0 = (((n0w + lB) * MROW + wB) << 2);
    const uint32_t rbB1 = (((n0w + 16 + lB) * MROW + wB) << 2);

    issue(0);
    for (int ch = 0; ch < 61; ++ch) {
        const int buf = ch & 1;
        CP_WAIT0();
        __syncthreads();
        issue(ch + 1);

        const uint32_t aAh = smem_u32(MS[buf][0]) + rbA;
        const uint32_t aAl = smem_u32(MS[buf][1]) + rbA;
        const uint32_t aB0h = smem_u32(MS[buf][2]) + rbB0;
        const uint32_t aB1h = smem_u32(MS[buf][2]) + rbB1;
        const uint32_t aB0l = smem_u32(MS[buf][3]) + rbB0;
        const uint32_t aB1l = smem_u32(MS[buf][3]) + rbB1;

        #pragma unroll
        for (int s = 0; s < 2; ++s) {
            uint32_t ahf[4], alf[4], bh[2][4], bl2[2][4];
            LDSM4(ahf, aAh + s * 32);
            LDSM4(alf, aAl + s * 32);
            LDSM4(bh[0], aB0h + s * 32);
            LDSM4(bh[1], aB1h + s * 32);
            LDSM4(bl2[0], aB0l + s * 32);
            LDSM4(bl2[1], aB1l + s * 32);
            #pragma unroll
            for (int ni = 0; ni < 4; ++ni) {
                mma16(cM[ni], ahf, bh[ni >> 1] + 2 * (ni & 1));
                mma16h(crM[ni], ahf, bl2[ni >> 1] + 2 * (ni & 1));
                mma16h(crM[ni], alf, bh[ni >> 1] + 2 * (ni & 1));
            }
        }
    }

    #pragma unroll
    for (int ni = 0; ni < 4; ++ni) {
        merge_cor(cM[ni], crM[ni]);
        int col = n0 + n0w + ni * 8 + 2 * t;
        *(float2*)(g_hpart + ((size_t)z * BCN + bc0 + m0 + g) * PREDN + col) =
            make_float2(cM[ni][0], cM[ni][1]);
        *(float2*)(g_hpart + ((size_t)z * BCN + bc0 + m0 + g + 8) * PREDN + col) =
            make_float2(cM[ni][2], cM[ni][3]);
    }
}

// ---------------- Kernel C2: reduce + GELU + @W2 (8 bc/block) -----------------
__global__ void __launch_bounds__(256)
mlp2_kernel(const float* __restrict__ b1, const float* __restrict__ W2,
            const float* __restrict__ b2, float* __restrict__ out) {
    __shared__ float hs[8][PREDN];
    const int bc0 = blockIdx.x * 8;
    const int nh  = blockIdx.y;
    const int tid = threadIdx.x;

    for (int i = tid; i < 8 * PREDN; i += 256) {
        int r = i >> 8, n = i & 255;
        int bc = bc0 + r;
        float v = b1[n];
        #pragma unroll
        for (int ks = 0; ks < NSPL; ++ks)
            v += g_hpart[((size_t)ks * BCN + bc) * PREDN + n];
        hs[r][n] = 0.5f * v * (1.f + erff(v * 0.70710678118654752f));
    }
    __syncthreads();

    const int r4 = (tid >> 7) * 4;
    const int n  = nh * 128 + (tid & 127);
    float acc[4] = {0.f, 0.f, 0.f, 0.f};
    #pragma unroll 4
    for (int k = 0; k < PREDN; ++k) {
        float w = W2[k * PREDN + n];
        acc[0] += hs[r4 + 0][k] * w;
        acc[1] += hs[r4 + 1][k] * w;
        acc[2] += hs[r4 + 2][k] * w;
        acc[3] += hs[r4 + 3][k] * w;
    }
    float bb = b2[n];
    #pragma unroll
    for (int r = 0; r < 4; ++r)
        out[(size_t)(bc0 + r4 + r) * PREDN + n] = acc[r] + bb;
}

// ---------------- launch ------------------------------------------------------
extern "C" void kernel_launch(void* const* d_in, const int* in_sizes, int n_in,
                              void* d_out, int out_size) {
    const float* lb  = (const float*)d_in[0];
    const float* fp  = (const float*)d_in[1];
    const float* Wp  = (const float*)d_in[2];
    const float* bp  = (const float*)d_in[3];
    const float* pe  = (const float*)d_in[4];
    const float* lng = (const float*)d_in[5];
    const float* lnb = (const float*)d_in[6];
    const float* W1  = (const float*)d_in[7];
    const float* b1  = (const float*)d_in[8];
    const float* W2  = (const float*)d_in[9];
    const float* b2  = (const float*)d_in[10];
    float* out = (float*)d_out;

    cudaFuncSetAttribute(proj_ln_kernel, cudaFuncAttributeMaxDynamicSharedMemorySize,
                         PROJ_BYTES);
    cudaFuncSetAttribute(attn_kernel, cudaFuncAttributeMaxDynamicSharedMemorySize,
                         ASM_BYTES);

    conv_wp_kernel<<<32, 256>>>(Wp);
    conv_w1_kernel<<<dim3(FLATN / 64, 4), 256>>>(W1);
    proj_ln_kernel<<<dim3(5, BCN), 256, PROJ_BYTES>>>(lb, fp, bp, pe, lng, lnb);
    attn_kernel<<<dim3(2, BCN), 256, ASM_BYTES>>>(lb, fp);
    mlp1_kernel<<<dim3(4, 8, NSPL), 256>>>();
    mlp2_kernel<<<dim3(BCN / 8, 2), 256>>>(b1, W2, b2, out);
}

// round 15
// speedup vs baseline: 1.0623x; 1.0623x over previous
#include <cuda_runtime.h>
#include <cuda_fp16.h>
#include <math.h>
#include <stdint.h>

#define BCN   512          // B*C
#define LBK   1024
#define PREDN 256
#define TOT   1280
#define DEL   64
#define DPD   128
#define NKR   971          // key rows (T)
#define NQR   244          // query rows (UP)
#define NROWS 1215         // NKR + NQR
#define FLATN 15616        // NQR*DEL
#define NSPL  8            // mlp1 split-K

// ---------------- scratch ------------------------------------------------------
__device__ __half g_kh[(size_t)BCN * NROWS * DPD];   // LN output, hi plane
__device__ __half g_kl[(size_t)BCN * NROWS * DPD];   // LN output, lo plane
__device__ __half g_fh[(size_t)BCN * FLATN];         // attention out, hi plane
__device__ __half g_fl[(size_t)BCN * FLATN];         // attention out, lo plane
__device__ __half g_w1h[(size_t)PREDN * FLATN];      // W1^T hi plane [n][k]
__device__ __half g_w1l[(size_t)PREDN * FLATN];      // W1^T lo plane [n][k]
__device__ __half g_wph[DPD * DEL];                  // Wp^T hi plane [e][d]
__device__ __half g_wpl[DPD * DEL];                  // Wp^T lo plane [e][d]
__device__ float  g_hpart[NSPL * BCN * PREDN];       // split-K partials

__device__ __forceinline__ float series_at(const float* __restrict__ lb,
                                           const float* __restrict__ fp,
                                           int bc, int i) {
    return (i < LBK) ? lb[bc * LBK + i] : fp[bc * PREDN + (i - LBK)];
}

// ---------------- PTX helpers ---------------------------------------------------
__device__ __forceinline__ uint32_t smem_u32(const void* p) {
    uint32_t a;
    asm("{ .reg .u64 t; cvta.to.shared.u64 t, %1; cvt.u32.u64 %0, t; }" : "=r"(a) : "l"(p));
    return a;
}

#define LDSM4(R, A) \
    asm volatile("ldmatrix.sync.aligned.m8n8.x4.shared.b16 {%0,%1,%2,%3}, [%4];" \
        : "=r"((R)[0]), "=r"((R)[1]), "=r"((R)[2]), "=r"((R)[3]) : "r"(A))

#define CP_A16(dst, src, sz) \
    asm volatile("cp.async.cg.shared.global [%0], [%1], 16, %2;" \
        :: "r"(dst), "l"(src), "r"(sz))
#define CP_COMMIT() asm volatile("cp.async.commit_group;" ::: "memory")
#define CP_WAIT0()  asm volatile("cp.async.wait_group 0;" ::: "memory")

__device__ __forceinline__ void mma16(float c[4], const uint32_t a[4], const uint32_t b[2]) {
    asm volatile(
        "mma.sync.aligned.m16n8k16.row.col.f32.f16.f16.f32 "
        "{%0,%1,%2,%3}, {%4,%5,%6,%7}, {%8,%9}, {%0,%1,%2,%3};\n"
        : "+f"(c[0]), "+f"(c[1]), "+f"(c[2]), "+f"(c[3])
        : "r"(a[0]), "r"(a[1]), "r"(a[2]), "r"(a[3]), "r"(b[0]), "r"(b[1]));
}

__device__ __forceinline__ void mma16h(uint32_t c[2], const uint32_t a[4], const uint32_t b[2]) {
    asm volatile(
        "mma.sync.aligned.m16n8k16.row.col.f16.f16.f16.f16 "
        "{%0,%1}, {%2,%3,%4,%5}, {%6,%7}, {%0,%1};\n"
        : "+r"(c[0]), "+r"(c[1])
        : "r"(a[0]), "r"(a[1]), "r"(a[2]), "r"(a[3]), "r"(b[0]), "r"(b[1]));
}

__device__ __forceinline__ void merge_cor(float c[4], const uint32_t cor[2]) {
    float2 a = __half22float2(*(const __half2*)&cor[0]);
    float2 b = __half22float2(*(const __half2*)&cor[1]);
    c[0] += a.x; c[1] += a.y; c[2] += b.x; c[3] += b.y;
}

__device__ __forceinline__ void hsplit2(float x0, float x1, uint32_t& hi, uint32_t& lo) {
    __half h0 = __float2half_rn(x0), h1 = __float2half_rn(x1);
    __half l0 = __float2half_rn(x0 - __half2float(h0));
    __half l1 = __float2half_rn(x1 - __half2float(h1));
    __half2 H = __halves2half2(h0, h1), L = __halves2half2(l0, l1);
    hi = *(uint32_t*)&H; lo = *(uint32_t*)&L;
}

__device__ __forceinline__ void hsplit1(float x, __half& h, __half& l) {
    h = __float2half_rn(x);
    l = __float2half_rn(x - __half2float(h));
}

__device__ __forceinline__ float ex2(float x) {
    float r;
    asm("ex2.approx.f32 %0, %1;" : "=f"(r) : "f"(x));
    return r;
}

// ---------------- Kernel W0: split Wp into transposed fp16 planes -------------
__global__ void __launch_bounds__(256)
conv_wp_kernel(const float* __restrict__ Wp) {
    int i = blockIdx.x * 256 + threadIdx.x;   // 8192 total
    int d = i >> 7, e = i & 127;
    float w = Wp[i];
    __half h, l; hsplit1(w, h, l);
    g_wph[e * DEL + d] = h;
    g_wpl[e * DEL + d] = l;
}

// ---------------- Kernel A: proj + PE + LN (256 rows/block) -------------------
#define PKW 36
#define PROJ_HDR_W (TOT + 256 + 256 + 128 + 128 + 128)
#define PROJ_BYTES (PROJ_HDR_W * 4 + 4 * 128 * PKW * 4)

__global__ void __launch_bounds__(256)
proj_ln_kernel(const float* __restrict__ lb, const float* __restrict__ fp,
               const float* __restrict__ bp, const float* __restrict__ pe,
               const float* __restrict__ lng, const float* __restrict__ lnb) {
    extern __shared__ float psm[];
    float* ssp   = psm;
    float* red_s = ssp + TOT;
    float* red_q = red_s + 256;
    float* gl_s  = red_q + 256;
    float* lb_s  = gl_s + 128;
    float* bp_s  = lb_s + 128;
    uint32_t* Ah = (uint32_t*)(bp_s + 128);
    uint32_t* Al = Ah + 128 * PKW;
    uint32_t* Bh = Al + 128 * PKW;
    uint32_t* Bl = Bh + 128 * PKW;

    const int bc  = blockIdx.y;
    const int tid = threadIdx.x;
    const int warp = tid >> 5, lane = tid & 31;
    const int g = lane >> 2, t = lane & 3;
    const int wm = warp >> 1, wn = warp & 1;
    const int R0 = wm * 32, C0 = wn * 64;

    for (int i = tid; i < TOT; i += 256) ssp[i] = series_at(lb, fp, bc, i);
    if (tid < 128) { gl_s[tid] = lng[tid]; lb_s[tid] = lnb[tid]; bp_s[tid] = bp[tid]; }

    __half* Ahb = (__half*)Ah;
    __half* Alb = (__half*)Al;
    __half* Bhb = (__half*)Bh;
    __half* Blb = (__half*)Bl;

    {
        const uint4* wph = (const uint4*)g_wph;
        const uint4* wpl = (const uint4*)g_wpl;
        for (int i = tid; i < 2048; i += 256) {
            int pl = i >> 10, r = (i >> 3) & 127, c = i & 7;
            uint4 v = pl ? wpl[r * 8 + c] : wph[r * 8 + c];
            uint4* dst = (uint4*)((pl ? Blb : Bhb) + r * (2 * PKW));
            dst[c] = v;
        }
    }
    __syncthreads();

    for (int h2 = 0; h2 < 2; ++h2) {
        const int t0 = blockIdx.x * 256 + h2 * 128;
        if (t0 >= NROWS) break;

        for (int i = tid; i < 128 * DEL; i += 256) {
            int r = i >> 6, d = i & 63;
            int tt = t0 + r;
            float x = 0.f;
            if (tt < NROWS) {
                int s0 = (tt < NKR) ? tt : (tt + 1);
                x = ssp[s0 + d];
            }
            __half h, l; hsplit1(x, h, l);
            Ahb[r * (2 * PKW) + d] = h;
            Alb[r * (2 * PKW) + d] = l;
        }
        __syncthreads();

        float cC[2][8][4];
        uint32_t cr[2][8][2];
        #pragma unroll
        for (int mi = 0; mi < 2; ++mi)
            #pragma unroll
            for (int ni = 0; ni < 8; ++ni) {
                #pragma unroll
                for (int i = 0; i < 4; ++i) cC[mi][ni][i] = 0.f;
                cr[mi][ni][0] = 0u; cr[mi][ni][1] = 0u;
            }

        #pragma unroll
        for (int e8 = 0; e8 < 4; ++e8) {
            uint32_t ah[2][4], al_[2][4];
            #pragma unroll
            for (int mi = 0; mi < 2; ++mi) {
                int r0 = (R0 + mi * 16 + g) * PKW + e8 * 8 + t;
                ah[mi][0] = Ah[r0];           ah[mi][1] = Ah[r0 + 8 * PKW];
                ah[mi][2] = Ah[r0 + 4];       ah[mi][3] = Ah[r0 + 8 * PKW + 4];
                al_[mi][0] = Al[r0];          al_[mi][1] = Al[r0 + 8 * PKW];
                al_[mi][2] = Al[r0 + 4];      al_[mi][3] = Al[r0 + 8 * PKW + 4];
            }
            uint32_t bh[8][2], bl2[8][2];
            #pragma unroll
            for (int ni = 0; ni < 8; ++ni) {
                int n0 = (C0 + ni * 8 + g) * PKW + e8 * 8 + t;
                bh[ni][0] = Bh[n0];  bh[ni][1] = Bh[n0 + 4];
                bl2[ni][0] = Bl[n0]; bl2[ni][1] = Bl[n0 + 4];
            }
            #pragma unroll
            for (int mi = 0; mi < 2; ++mi)
                #pragma unroll
                for (int ni = 0; ni < 8; ++ni) {
                    mma16(cC[mi][ni], ah[mi], bh[ni]);
                    mma16h(cr[mi][ni], ah[mi], bl2[ni]);
                    mma16h(cr[mi][ni], al_[mi], bh[ni]);
                }
        }
        #pragma unroll
        for (int mi = 0; mi < 2; ++mi)
            #pragma unroll
            for (int ni = 0; ni < 8; ++ni) merge_cor(cC[mi][ni], cr[mi][ni]);

        float ps_[2][2], pq_[2][2];
        #pragma unroll
        for (int mi = 0; mi < 2; ++mi)
            #pragma unroll
            for (int h = 0; h < 2; ++h) { ps_[mi][h] = 0.f; pq_[mi][h] = 0.f; }

        #pragma unroll
        for (int mi = 0; mi < 2; ++mi)
            #pragma unroll
            for (int h = 0; h < 2; ++h) {
                int row = R0 + mi * 16 + g + 8 * h;
                int grow = t0 + row;
                const float* perow = pe + (size_t)grow * DPD;
                #pragma unroll
                for (int ni = 0; ni < 8; ++ni) {
                    int col = C0 + ni * 8 + 2 * t;
                    float2 p2 = *(const float2*)(perow + col);
                    float x0 = cC[mi][ni][2 * h]     + bp_s[col]     + p2.x;
                    float x1 = cC[mi][ni][2 * h + 1] + bp_s[col + 1] + p2.y;
                    cC[mi][ni][2 * h] = x0; cC[mi][ni][2 * h + 1] = x1;
                    ps_[mi][h] += x0 + x1;
                    pq_[mi][h] += x0 * x0 + x1 * x1;
                }
            }
        #pragma unroll
        for (int mi = 0; mi < 2; ++mi)
            #pragma unroll
            for (int h = 0; h < 2; ++h) {
                ps_[mi][h] += __shfl_xor_sync(0xffffffffu, ps_[mi][h], 1);
                ps_[mi][h] += __shfl_xor_sync(0xffffffffu, ps_[mi][h], 2);
                pq_[mi][h] += __shfl_xor_sync(0xffffffffu, pq_[mi][h], 1);
                pq_[mi][h] += __shfl_xor_sync(0xffffffffu, pq_[mi][h], 2);
            }
        if (t == 0) {
            #pragma unroll
            for (int mi = 0; mi < 2; ++mi)
                #pragma unroll
                for (int h = 0; h < 2; ++h) {
                    int row = R0 + mi * 16 + g + 8 * h;
                    red_s[wn * 128 + row] = ps_[mi][h];
                    red_q[wn * 128 + row] = pq_[mi][h];
                }
        }
        __syncthreads();

        #pragma unroll
        for (int mi = 0; mi < 2; ++mi)
            #pragma unroll
            for (int h = 0; h < 2; ++h) {
                int row = R0 + mi * 16 + g + 8 * h;
                int grow = t0 + row;
                if (grow >= NROWS) continue;
                float sm_ = red_s[row] + red_s[128 + row];
                float sq_ = red_q[row] + red_q[128 + row];
                float mean = sm_ * (1.f / DPD);
                float var  = sq_ * (1.f / DPD) - mean * mean;
                float inv  = rsqrtf(var + 1e-5f);
                size_t base = ((size_t)bc * NROWS + grow) * DPD;
                #pragma unroll
                for (int ni = 0; ni < 8; ++ni) {
                    int col = C0 + ni * 8 + 2 * t;
                    float y0 = (cC[mi][ni][2 * h]     - mean) * inv * gl_s[col]     + lb_s[col];
                    float y1 = (cC[mi][ni][2 * h + 1] - mean) * inv * gl_s[col + 1] + lb_s[col + 1];
                    uint32_t hw, lw; hsplit2(y0, y1, hw, lw);
                    *(uint32_t*)(g_kh + base + col) = hw;
                    *(uint32_t*)(g_kl + base + col) = lw;
                }
            }
        __syncthreads();
    }
}

// ---------------- Kernel B: attention (Q-hoisted, chained V, mask-spec) -------
#define KW 68
#define VPN 642
#define QH_W (TOT + 4 * VPN)              // 3848 words
#define KB_W (QH_W + 2 * 128 * KW)        // 21256 words
#define ATT_W (KB_W + 4 * 128 * KW)       // 56072 words
#define ASM_BYTES (ATT_W * 4)             // 224288 bytes

__global__ void __launch_bounds__(256, 1)
attn_kernel(const float* __restrict__ lb, const float* __restrict__ fp) {
    extern __shared__ float sm[];
    float* ss     = sm;                        // [1280]
    uint32_t* vph = (uint32_t*)(sm + TOT);     // [2*VPN]
    uint32_t* vpl = vph + 2 * VPN;             // [2*VPN]
    uint32_t* qh  = (uint32_t*)sm + QH_W;      // [128*KW]
    uint32_t* ql  = qh + 128 * KW;

    const uint32_t sbase = smem_u32(sm);
    const uint32_t kb_a  = sbase + KB_W * 4;

    const int bc  = blockIdx.y;
    const int qt0 = blockIdx.x * 128;
    const int tid = threadIdx.x;
    const int warp = tid >> 5, lane = tid & 31;
    const int g = lane >> 2, t = lane & 3;
    const int q0 = warp * 16;

    const int lA = lane & 15, wA = (lane >> 4) * 4;
    const int lB = (lane & 7) + ((lane >> 4) & 1) * 8;
    const int wB = ((lane >> 3) & 1) * 4;

    auto issue_chunk = [&](int ch) {
        if (ch >= 8) return;
        const int buf = ch & 1;
        const uint32_t dkh = kb_a + buf * 69632u;
        const uint32_t dkl = dkh + 34816u;
        const int kt0 = ch * 128;
        const uint4* gh = (const uint4*)(g_kh + ((size_t)bc * NROWS + kt0) * DPD);
        const uint4* gl = (const uint4*)(g_kl + ((size_t)bc * NROWS + kt0) * DPD);
        #pragma unroll
        for (int it = 0; it < 8; ++it) {
            int i = tid + it * 256;
            int r = i >> 4, c = i & 15;
            int sz = (kt0 + r < NKR) ? 16 : 0;
            uint32_t d = (uint32_t)((r * 17 + c) * 16);
            CP_A16(dkh + d, gh + r * 16 + c, sz);
            CP_A16(dkl + d, gl + r * 16 + c, sz);
        }
        CP_COMMIT();
    };

    issue_chunk(0);

    for (int i = tid; i < TOT; i += 256) ss[i] = series_at(lb, fp, bc, i);

    {
        const uint4* qhs = (const uint4*)(g_kh + ((size_t)bc * NROWS + NKR + qt0) * DPD);
        const uint4* qls = (const uint4*)(g_kl + ((size_t)bc * NROWS + NKR + qt0) * DPD);
        uint4 z = make_uint4(0u, 0u, 0u, 0u);
        for (int i = tid; i < 128 * 16; i += 256) {
            int r = i >> 4, c = i & 15;
            bool v = (qt0 + r) < NQR;
            ((uint4*)qh)[r * 17 + c] = v ? qhs[r * 16 + c] : z;
            ((uint4*)ql)[r * 17 + c] = v ? qls[r * 16 + c] : z;
        }
    }

    for (int i = tid; i < 2 * 641; i += 256) {
        int par = (i >= 641);
        int w = i - par * 641;
        int e0 = 2 * w + par;
        float x0 = (e0 < TOT) ? ss[e0] : 0.f;
        float x1 = (e0 + 1 < TOT) ? ss[e0 + 1] : 0.f;
        uint32_t hw, lw; hsplit2(x0, x1, hw, lw);
        vph[par * VPN + w] = hw;
        vpl[par * VPN + w] = lw;
    }
    __syncthreads();   // Q/V staged and visible

    // ---- hoist Q fragments (chunk- and j-invariant): 64 regs ----
    const uint32_t aQH = smem_u32(qh) + (((q0 + lA) * KW + wA) << 2);
    const uint32_t aQL = smem_u32(ql) + (((q0 + lA) * KW + wA) << 2);
    uint32_t qa_h[8][4], qa_l[8][4];
    #pragma unroll
    for (int e8 = 0; e8 < 8; ++e8) {
        LDSM4(qa_h[e8], aQH + e8 * 32);
        LDSM4(qa_l[e8], aQL + e8 * 32);
    }

    uint32_t rbK[8];
    #pragma unroll
    for (int n2 = 0; n2 < 8; ++n2)
        rbK[n2] = (((n2 * 16 + lB) * KW + wB) << 2);

    const int vpar = (1 + g) & 1;
    const uint32_t vparoff = (uint32_t)(vpar * VPN);

    float cO[8][4];
    uint32_t crO[8][2];
    float rs0 = 0.f, rs1 = 0.f;
    #pragma unroll
    for (int ni = 0; ni < 8; ++ni) {
        #pragma unroll
        for (int i = 0; i < 4; ++i) cO[ni][i] = 0.f;
        crO[ni][0] = 0u; crO[ni][1] = 0u;
    }

    const float C2  = 0.1275174324f;     // log2(e)/sqrt(128)
    const float OFF = -8.6561702453f;    // -6*log2(e)

    for (int ch = 0; ch < 8; ++ch) {
        const int kt0 = ch * 128;
        const int buf = ch & 1;
        const uint32_t kh_a = kb_a + buf * 69632u;
        const uint32_t kl_a = kh_a + 34816u;
        const bool needmask = (kt0 + 128 > NKR);

        CP_WAIT0();
        __syncthreads();   // K chunk ready; buf^1 free
        issue_chunk(ch + 1);

        const int vb0 = kt0 + 1;
        #pragma unroll
        for (int j = 0; j < 8; ++j) {
            float cS[2][4];
            uint32_t crS[2][2];
            #pragma unroll
            for (int jj = 0; jj < 2; ++jj) {
                #pragma unroll
                for (int i = 0; i < 4; ++i) cS[jj][i] = 0.f;
                crS[jj][0] = 0u; crS[jj][1] = 0u;
            }

            #pragma unroll
            for (int e8 = 0; e8 < 8; ++e8) {
                uint32_t b_h[4], b_l[4];
                LDSM4(b_h, kh_a + rbK[j] + e8 * 32);
                LDSM4(b_l, kl_a + rbK[j] + e8 * 32);
                mma16(cS[0], qa_h[e8], b_h);
                mma16h(crS[0], qa_h[e8], b_l);
                mma16h(crS[0], qa_l[e8], b_h);
                mma16(cS[1], qa_h[e8], b_h + 2);
                mma16h(crS[1], qa_h[e8], b_l + 2);
                mma16h(crS[1], qa_l[e8], b_h + 2);
            }

            float p[8];
            if (!needmask) {
                #pragma unroll
                for (int jj = 0; jj < 2; ++jj) {
                    merge_cor(cS[jj], crS[jj]);
                    float p0 = ex2(fmaf(cS[jj][0], C2, OFF));
                    float p1 = ex2(fmaf(cS[jj][1], C2, OFF));
                    float p2 = ex2(fmaf(cS[jj][2], C2, OFF));
                    float p3 = ex2(fmaf(cS[jj][3], C2, OFF));
                    rs0 += p0 + p1;
                    rs1 += p2 + p3;
                    p[4 * jj + 0] = p0; p[4 * jj + 1] = p1;
                    p[4 * jj + 2] = p2; p[4 * jj + 3] = p3;
                }
            } else {
                #pragma unroll
                for (int jj = 0; jj < 2; ++jj) {
                    merge_cor(cS[jj], crS[jj]);
                    int c0 = kt0 + 16 * j + 8 * jj + 2 * t;
                    float p0 = (c0     < NKR) ? ex2(fmaf(cS[jj][0], C2, OFF)) : 0.f;
                    float p1 = (c0 + 1 < NKR) ? ex2(fmaf(cS[jj][1], C2, OFF)) : 0.f;
                    float p2 = (c0     < NKR) ? ex2(fmaf(cS[jj][2], C2, OFF)) : 0.f;
                    float p3 = (c0 + 1 < NKR) ? ex2(fmaf(cS[jj][3], C2, OFF)) : 0.f;
                    rs0 += p0 + p1;
                    rs1 += p2 + p3;
                    p[4 * jj + 0] = p0; p[4 * jj + 1] = p1;
                    p[4 * jj + 2] = p2; p[4 * jj + 3] = p3;
                }
            }
            uint32_t ah[4], al[4];
            hsplit2(p[0], p[1], ah[0], al[0]);
            hsplit2(p[2], p[3], ah[1], al[1]);
            hsplit2(p[4], p[5], ah[2], al[2]);
            hsplit2(p[6], p[7], ah[3], al[3]);

            const uint32_t wb = (uint32_t)((vb0 + j * 16 + 2 * t + g) >> 1) + vparoff;
            uint32_t vh0 = vph[wb], vl0 = vpl[wb];
            #pragma unroll
            for (int ni = 0; ni < 8; ++ni) {
                uint32_t vh1 = vph[wb + 4 * (ni + 1)];
                uint32_t vl1 = vpl[wb + 4 * (ni + 1)];
                uint32_t vhp[2] = {vh0, vh1};
                uint32_t vlp[2] = {vl0, vl1};
                mma16(cO[ni], ah, vhp);
                mma16h(crO[ni], ah, vlp);
                mma16h(crO[ni], al, vhp);
                vh0 = vh1; vl0 = vl1;
            }
        }
    }

    rs0 += __shfl_xor_sync(0xffffffffu, rs0, 1);
    rs0 += __shfl_xor_sync(0xffffffffu, rs0, 2);
    rs1 += __shfl_xor_sync(0xffffffffu, rs1, 1);
    rs1 += __shfl_xor_sync(0xffffffffu, rs1, 2);
    const float inv0 = 1.f / rs0;
    const float inv1 = 1.f / rs1;
    const int r0 = qt0 + q0 + g;

    #pragma unroll
    for (int ni = 0; ni < 8; ++ni) {
        merge_cor(cO[ni], crO[ni]);
        int d = ni * 8 + 2 * t;
        uint32_t hw, lw;
        if (r0 < NQR) {
            hsplit2(cO[ni][0] * inv0, cO[ni][1] * inv0, hw, lw);
            *(uint32_t*)(g_fh + (size_t)bc * FLATN + (size_t)r0 * DEL + d) = hw;
            *(uint32_t*)(g_fl + (size_t)bc * FLATN + (size_t)r0 * DEL + d) = lw;
        }
        if (r0 + 8 < NQR) {
            hsplit2(cO[ni][2] * inv1, cO[ni][3] * inv1, hw, lw);
            *(uint32_t*)(g_fh + (size_t)bc * FLATN + (size_t)(r0 + 8) * DEL + d) = hw;
            *(uint32_t*)(g_fl + (size_t)bc * FLATN + (size_t)(r0 + 8) * DEL + d) = lw;
        }
    }
}

// ---------------- Kernel W1: split W1, coalesced via smem tile transpose ------
__global__ void __launch_bounds__(256)
conv_w1_kernel(const float* __restrict__ W1) {
    __shared__ float tile[64][65];
    const int k0 = blockIdx.x * 64;
    const int n0 = blockIdx.y * 64;
    const int tid = threadIdx.x;

    #pragma unroll
    for (int i = 0; i < 16; ++i) {
        int idx = tid + i * 256;
        int r = idx >> 6, c = idx & 63;
        tile[r][c] = W1[(size_t)(k0 + r) * PREDN + n0 + c];
    }
    __syncthreads();

    #pragma unroll
    for (int i = 0; i < 16; ++i) {
        int idx = tid + i * 256;
        int n = idx >> 6, k = idx & 63;
        float v = tile[k][n];
        __half h, l; hsplit1(v, h, l);
        size_t off = (size_t)(n0 + n) * FLATN + k0 + k;
        g_w1h[off] = h;
        g_w1l[off] = l;
    }
}

// ---------------- Kernel C1: flat @ W1 (ldmatrix + cp.async db) ---------------
#define MROW 20
__global__ void __launch_bounds__(256)
mlp1_kernel() {
    __shared__ __align__(16) uint32_t MS[2][4][64 * MROW];

    const int n0  = blockIdx.x * 64;
    const int bc0 = blockIdx.y * 64;
    const int z   = blockIdx.z;
    const int tid = threadIdx.x;
    const int warp = tid >> 5, lane = tid & 31;
    const int g = lane >> 2, t = lane & 3;
    const int lA = lane & 15, wA = (lane >> 4) * 4;
    const int lB = (lane & 7) + ((lane >> 4) & 1) * 8, wB = ((lane >> 3) & 1) * 4;
    const int m0  = (warp >> 1) * 16;
    const int n0w = (warp & 1) * 32;
    const int r4 = tid >> 2, c4 = tid & 3;

    auto issue = [&](int ch) {
        if (ch >= 61) return;
        const int buf = ch & 1;
        const int k0 = z * 1952 + ch * 32;
        const uint4* sh[4] = {
            (const uint4*)(g_fh  + (size_t)(bc0 + r4) * FLATN + k0),
            (const uint4*)(g_fl  + (size_t)(bc0 + r4) * FLATN + k0),
            (const uint4*)(g_w1h + (size_t)(n0 + r4) * FLATN + k0),
            (const uint4*)(g_w1l + (size_t)(n0 + r4) * FLATN + k0)};
        uint32_t d = (uint32_t)((r4 * 5 + c4) * 16);
        #pragma unroll
        for (int p = 0; p < 4; ++p)
            CP_A16(smem_u32(MS[buf][p]) + d, sh[p] + c4, 16);
        CP_COMMIT();
    };

    float cM[4][4];
    uint32_t crM[4][2];
    #pragma unroll
    for (int ni = 0; ni < 4; ++ni) {
        #pragma unroll
        for (int i = 0; i < 4; ++i) cM[ni][i] = 0.f;
        crM[ni][0] = 0u; crM[ni][1] = 0u;
    }

    const uint32_t rbA = (((m0 + lA) * MROW + wA) << 2);
    const uint32_t rbB0 = (((n0w + lB) * MROW + wB) << 2);
    const uint32_t rbB1 = (((n0w + 16 + lB) * MROW + wB) << 2);

    issue(0);
    for (int ch = 0; ch < 61; ++ch) {
        const int buf = ch & 1;
        CP_WAIT0();
        __syncthreads();
        issue(ch + 1);

        const uint32_t aAh = smem_u32(MS[buf][0]) + rbA;
        const uint32_t aAl = smem_u32(MS[buf][1]) + rbA;
        const uint32_t aB0h = smem_u32(MS[buf][2]) + rbB0;
        const uint32_t aB1h = smem_u32(MS[buf][2]) + rbB1;
        const uint32_t aB0l = smem_u32(MS[buf][3]) + rbB0;
        const uint32_t aB1l = smem_u32(MS[buf][3]) + rbB1;

        #pragma unroll
        for (int s = 0; s < 2; ++s) {
            uint32_t ahf[4], alf[4], bh[2][4], bl2[2][4];
            LDSM4(ahf, aAh + s * 32);
            LDSM4(alf, aAl + s * 32);
            LDSM4(bh[0], aB0h + s * 32);
            LDSM4(bh[1], aB1h + s * 32);
            LDSM4(bl2[0], aB0l + s * 32);
            LDSM4(bl2[1], aB1l + s * 32);
            #pragma unroll
            for (int ni = 0; ni < 4; ++ni) {
                mma16(cM[ni], ahf, bh[ni >> 1] + 2 * (ni & 1));
                mma16h(crM[ni], ahf, bl2[ni >> 1] + 2 * (ni & 1));
                mma16h(crM[ni], alf, bh[ni >> 1] + 2 * (ni & 1));
            }
        }
    }

    #pragma unroll
    for (int ni = 0; ni < 4; ++ni) {
        merge_cor(cM[ni], crM[ni]);
        int col = n0 + n0w + ni * 8 + 2 * t;
        *(float2*)(g_hpart + ((size_t)z * BCN + bc0 + m0 + g) * PREDN + col) =
            make_float2(cM[ni][0], cM[ni][1]);
        *(float2*)(g_hpart + ((size_t)z * BCN + bc0 + m0 + g + 8) * PREDN + col) =
            make_float2(cM[ni][2], cM[ni][3]);
    }
}

// ---------------- Kernel C2: reduce + GELU + @W2 (8 bc/block) -----------------
__global__ void __launch_bounds__(256)
mlp2_kernel(const float* __restrict__ b1, const float* __restrict__ W2,
            const float* __restrict__ b2, float* __restrict__ out) {
    __shared__ float hs[8][PREDN];
    const int bc0 = blockIdx.x * 8;
    const int nh  = blockIdx.y;
    const int tid = threadIdx.x;

    for (int i = tid; i < 8 * PREDN; i += 256) {
        int r = i >> 8, n = i & 255;
        int bc = bc0 + r;
        float v = b1[n];
        #pragma unroll
        for (int ks = 0; ks < NSPL; ++ks)
            v += g_hpart[((size_t)ks * BCN + bc) * PREDN + n];
        hs[r][n] = 0.5f * v * (1.f + erff(v * 0.70710678118654752f));
    }
    __syncthreads();

    const int r4 = (tid >> 7) * 4;
    const int n  = nh * 128 + (tid & 127);
    float acc[4] = {0.f, 0.f, 0.f, 0.f};
    #pragma unroll 4
    for (int k = 0; k < PREDN; ++k) {
        float w = W2[k * PREDN + n];
        acc[0] += hs[r4 + 0][k] * w;
        acc[1] += hs[r4 + 1][k] * w;
        acc[2] += hs[r4 + 2][k] * w;
        acc[3] += hs[r4 + 3][k] * w;
    }
    float bb = b2[n];
    #pragma unroll
    for (int r = 0; r < 4; ++r)
        out[(size_t)(bc0 + r4 + r) * PREDN + n] = acc[r] + bb;
}

// ---------------- launch ------------------------------------------------------
extern "C" void kernel_launch(void* const* d_in, const int* in_sizes, int n_in,
                              void* d_out, int out_size) {
    const float* lb  = (const float*)d_in[0];
    const float* fp  = (const float*)d_in[1];
    const float* Wp  = (const float*)d_in[2];
    const float* bp  = (const float*)d_in[3];
    const float* pe  = (const float*)d_in[4];
    const float* lng = (const float*)d_in[5];
    const float* lnb = (const float*)d_in[6];
    const float* W1  = (const float*)d_in[7];
    const float* b1  = (const float*)d_in[8];
    const float* W2  = (const float*)d_in[9];
    const float* b2  = (const float*)d_in[10];
    float* out = (float*)d_out;

    cudaFuncSetAttribute(proj_ln_kernel, cudaFuncAttributeMaxDynamicSharedMemorySize,
                         PROJ_BYTES);
    cudaFuncSetAttribute(attn_kernel, cudaFuncAttributeMaxDynamicSharedMemorySize,
                         ASM_BYTES);

    conv_wp_kernel<<<32, 256>>>(Wp);
    conv_w1_kernel<<<dim3(FLATN / 64, 4), 256>>>(W1);
    proj_ln_kernel<<<dim3(5, BCN), 256, PROJ_BYTES>>>(lb, fp, bp, pe, lng, lnb);
    attn_kernel<<<dim3(2, BCN), 256, ASM_BYTES>>>(lb, fp);
    mlp1_kernel<<<dim3(4, 8, NSPL), 256>>>();
    mlp2_kernel<<<dim3(BCN / 8, 2), 256>>>(b1, W2, b2, out);
}